// round 1
// baseline (speedup 1.0000x reference)
#include <cuda_runtime.h>

#define NB   8
#define LSEQ 512
#define EDIM 1024
#define NH   16
#define HD   64

// Scratch for projected Q and K (16 MB each) — device globals, no allocation.
__device__ float g_Qp[NB * LSEQ * EDIM];
__device__ float g_Kp[NB * LSEQ * EDIM];

// C[m,n] = sum_k A[m,k] * W[n,k]   (A: [4096,1024] row-major, W: [1024,1024] row-major)
// 128x128 block tile, BK=16, 256 threads, 8x8 per-thread micro-tile.
__global__ void __launch_bounds__(256) proj_gemm(const float* __restrict__ A,
                                                 const float* __restrict__ W,
                                                 float* __restrict__ C) {
    __shared__ float As[16][132];
    __shared__ float Ws[16][132];
    const int tid = threadIdx.x;
    const int m0 = blockIdx.y * 128;
    const int n0 = blockIdx.x * 128;
    const int r  = tid >> 2;          // 0..63
    const int c4 = (tid & 3) * 4;     // 0,4,8,12
    const int ty = tid >> 4;          // 0..15
    const int tx = tid & 15;          // 0..15

    float acc[8][8];
#pragma unroll
    for (int i = 0; i < 8; i++)
#pragma unroll
        for (int j = 0; j < 8; j++) acc[i][j] = 0.f;

    for (int kt = 0; kt < EDIM; kt += 16) {
#pragma unroll
        for (int s = 0; s < 2; s++) {
            const int row = r + s * 64;
            float4 va = *reinterpret_cast<const float4*>(
                &A[(size_t)(m0 + row) * EDIM + kt + c4]);
            As[c4 + 0][row] = va.x; As[c4 + 1][row] = va.y;
            As[c4 + 2][row] = va.z; As[c4 + 3][row] = va.w;
            float4 vw = *reinterpret_cast<const float4*>(
                &W[(size_t)(n0 + row) * EDIM + kt + c4]);
            Ws[c4 + 0][row] = vw.x; Ws[c4 + 1][row] = vw.y;
            Ws[c4 + 2][row] = vw.z; Ws[c4 + 3][row] = vw.w;
        }
        __syncthreads();
#pragma unroll
        for (int k = 0; k < 16; k++) {
            float a[8], b[8];
            *reinterpret_cast<float4*>(&a[0]) =
                *reinterpret_cast<const float4*>(&As[k][ty * 8]);
            *reinterpret_cast<float4*>(&a[4]) =
                *reinterpret_cast<const float4*>(&As[k][ty * 8 + 4]);
            *reinterpret_cast<float4*>(&b[0]) =
                *reinterpret_cast<const float4*>(&Ws[k][tx * 8]);
            *reinterpret_cast<float4*>(&b[4]) =
                *reinterpret_cast<const float4*>(&Ws[k][tx * 8 + 4]);
#pragma unroll
            for (int i = 0; i < 8; i++)
#pragma unroll
                for (int j = 0; j < 8; j++)
                    acc[i][j] = fmaf(a[i], b[j], acc[i][j]);
        }
        __syncthreads();
    }
#pragma unroll
    for (int i = 0; i < 8; i++) {
        float4 o0 = make_float4(acc[i][0], acc[i][1], acc[i][2], acc[i][3]);
        float4 o1 = make_float4(acc[i][4], acc[i][5], acc[i][6], acc[i][7]);
        float* cp = &C[(size_t)(m0 + ty * 8 + i) * EDIM + n0 + tx * 8];
        *reinterpret_cast<float4*>(cp)     = o0;
        *reinterpret_cast<float4*>(cp + 4) = o1;
    }
}

// One block per (b, h, ktile of 64). out[b,h,k] = sum_a ln( sum_q exp(0.125 * Q[a,h,q,:].K[b,h,k,:]) )
// (the /SCALE, *SCALE and mean/8 cancel exactly against the 8 a-terms)
__global__ void __launch_bounds__(256) attn_energy(const float* __restrict__ Qp,
                                                   const float* __restrict__ Kp,
                                                   float* __restrict__ out) {
    const int kt = blockIdx.x;   // 0..7   (k tile)
    const int h  = blockIdx.y;   // 0..15
    const int b  = blockIdx.z;   // 0..7

    __shared__ float Ks[64][65];
    __shared__ float Qs[64][65];
    __shared__ float red[16][64];

    const int tid = threadIdx.x;
    const int tyq = tid >> 4;    // 0..15 : q sub-row group
    const int txk = tid & 15;    // 0..15 : k sub-col group

    // Load K tile once per block: 64 seq rows x 64 head dims
#pragma unroll
    for (int s = 0; s < 4; s++) {
        int fi  = tid + 256 * s;     // 0..1023 float4s
        int row = fi >> 4;
        int c4  = (fi & 15) * 4;
        float4 v = *reinterpret_cast<const float4*>(
            &Kp[((size_t)(b * LSEQ + kt * 64 + row)) * EDIM + h * HD + c4]);
        Ks[row][c4 + 0] = v.x; Ks[row][c4 + 1] = v.y;
        Ks[row][c4 + 2] = v.z; Ks[row][c4 + 3] = v.w;
    }

    float acc = 0.f;   // valid for tid < 64

    for (int a = 0; a < NB; a++) {
        float psum[4] = {0.f, 0.f, 0.f, 0.f};
        for (int qt = 0; qt < 8; qt++) {
            __syncthreads();   // protect Qs (and initial Ks load / red readers)
#pragma unroll
            for (int s = 0; s < 4; s++) {
                int fi  = tid + 256 * s;
                int row = fi >> 4;
                int c4  = (fi & 15) * 4;
                float4 v = *reinterpret_cast<const float4*>(
                    &Qp[((size_t)(a * LSEQ + qt * 64 + row)) * EDIM + h * HD + c4]);
                Qs[row][c4 + 0] = v.x; Qs[row][c4 + 1] = v.y;
                Qs[row][c4 + 2] = v.z; Qs[row][c4 + 3] = v.w;
            }
            __syncthreads();

            float sdot[4][4];
#pragma unroll
            for (int i = 0; i < 4; i++)
#pragma unroll
                for (int j = 0; j < 4; j++) sdot[i][j] = 0.f;

#pragma unroll
            for (int d = 0; d < 64; d++) {
                float qv[4], kv[4];
#pragma unroll
                for (int i = 0; i < 4; i++) qv[i] = Qs[tyq * 4 + i][d];
#pragma unroll
                for (int j = 0; j < 4; j++) kv[j] = Ks[txk * 4 + j][d];
#pragma unroll
                for (int i = 0; i < 4; i++)
#pragma unroll
                    for (int j = 0; j < 4; j++)
                        sdot[i][j] = fmaf(qv[i], kv[j], sdot[i][j]);
            }
            // logits ~ N(0,1): no max subtraction needed for fp32 exp
#pragma unroll
            for (int i = 0; i < 4; i++)
#pragma unroll
                for (int j = 0; j < 4; j++)
                    psum[j] += __expf(sdot[i][j] * 0.125f);
        }
        __syncthreads();
#pragma unroll
        for (int j = 0; j < 4; j++) red[tyq][txk * 4 + j] = psum[j];
        __syncthreads();
        if (tid < 64) {
            float sum = 0.f;
#pragma unroll
            for (int rr = 0; rr < 16; rr++) sum += red[rr][tid];
            acc += logf(sum);
        }
    }

    if (tid < 64)
        out[((size_t)b * NH + h) * LSEQ + kt * 64 + tid] = acc;
}

extern "C" void kernel_launch(void* const* d_in, const int* in_sizes, int n_in,
                              void* d_out, int out_size) {
    (void)in_sizes; (void)n_in; (void)out_size;
    const float* query  = (const float*)d_in[0];
    const float* memory = (const float*)d_in[1];
    const float* W_Q    = (const float*)d_in[2];
    const float* W_K    = (const float*)d_in[3];
    float* out = (float*)d_out;

    float *qp, *kp;
    cudaGetSymbolAddress((void**)&qp, g_Qp);
    cudaGetSymbolAddress((void**)&kp, g_Kp);

    dim3 gA(EDIM / 128, (NB * LSEQ) / 128);   // 8 x 32
    proj_gemm<<<gA, 256>>>(query,  W_Q, qp);
    proj_gemm<<<gA, 256>>>(memory, W_K, kp);

    dim3 gB(LSEQ / 64, NH, NB);               // 8 x 16 x 8
    attn_energy<<<gB, 256>>>(qp, kp, out);
}

// round 3
// speedup vs baseline: 3.5844x; 3.5844x over previous
#include <cuda_runtime.h>
#include <cstdint>

#define NB   8
#define LSEQ 512
#define EDIM 1024
#define NH   16
#define HD   64

// Projected Q/K scratch (tf32-rounded f32 bits), 16 MB each.
__device__ float g_Qp[NB * LSEQ * EDIM];
__device__ float g_Kp[NB * LSEQ * EDIM];

// ---------------- helpers ----------------
static __device__ __forceinline__ uint32_t smem_u32(const void* p) {
    uint32_t a;
    asm("{ .reg .u64 t; cvta.to.shared.u64 t, %1; cvt.u32.u64 %0, t; }"
        : "=r"(a) : "l"(p));
    return a;
}
static __device__ __forceinline__ float to_tf32(float x) {
    float r; asm("cvt.rna.tf32.f32 %0, %1;" : "=f"(r) : "f"(x)); return r;
}
static __device__ __forceinline__ float fast_ex2(float x) {
    float r; asm("ex2.approx.f32 %0, %1;" : "=f"(r) : "f"(x)); return r;
}
static __device__ __forceinline__ float fast_lg2(float x) {
    float r; asm("lg2.approx.f32 %0, %1;" : "=f"(r) : "f"(x)); return r;
}
static __device__ __forceinline__ void mma8(float c[4], const uint32_t a[4],
                                            const uint32_t b[2]) {
    asm volatile(
        "mma.sync.aligned.m16n8k8.row.col.f32.tf32.tf32.f32 "
        "{%0,%1,%2,%3},{%4,%5,%6,%7},{%8,%9},{%0,%1,%2,%3};"
        : "+f"(c[0]), "+f"(c[1]), "+f"(c[2]), "+f"(c[3])
        : "r"(a[0]), "r"(a[1]), "r"(a[2]), "r"(a[3]), "r"(b[0]), "r"(b[1]));
}
#define CP16(dst, src) \
    asm volatile("cp.async.cg.shared.global [%0], [%1], 16;" :: "r"(dst), "l"(src))
#define CP_COMMIT() asm volatile("cp.async.commit_group;")
#define CP_WAIT(n)  asm volatile("cp.async.wait_group %0;" :: "n"(n))

// ================= projection GEMM =================
// C[m,n] = sum_k A[m,k] * W[n,k]; A:[4096,1024], W:[1024,1024], C tf32-rounded.
// Block tile 128m x 256n, KC=16 double-buffered, 8 warps (2m x 4n), warp 64x64.
#define PPAD 20

__global__ void __launch_bounds__(256, 1)
proj_tc(const float* __restrict__ A, const float* __restrict__ W,
        float* __restrict__ C) {
    extern __shared__ float sm[];
    float* sA = sm;                  // 2 * 128 * PPAD
    float* sW = sm + 2 * 128 * PPAD; // 2 * 256 * PPAD
    const int tid = threadIdx.x, lane = tid & 31, wid = tid >> 5;
    const int wm = wid & 1, wn = wid >> 1, g = lane >> 2, tig = lane & 3;
    const int m0 = blockIdx.y * 128, n0 = blockIdx.x * 256;
    const int arow = tid >> 2, ac4 = (tid & 3) * 4;

    float acc[4][8][4];
#pragma unroll
    for (int i = 0; i < 4; i++)
#pragma unroll
        for (int j = 0; j < 8; j++)
#pragma unroll
            for (int k = 0; k < 4; k++) acc[i][j][k] = 0.f;

    float4 rA[2], rW[4];

    auto LOAD = [&](int kc) {
        const float* ap = A + (size_t)m0 * EDIM + kc * 16;
#pragma unroll
        for (int s = 0; s < 2; s++)
            rA[s] = *(const float4*)(ap + (size_t)(arow + 64 * s) * EDIM + ac4);
        const float* wp = W + (size_t)n0 * EDIM + kc * 16;
#pragma unroll
        for (int s = 0; s < 4; s++)
            rW[s] = *(const float4*)(wp + (size_t)(arow + 64 * s) * EDIM + ac4);
    };
    auto STORE = [&](int p) {
#pragma unroll
        for (int s = 0; s < 2; s++) {
            float* d = &sA[p * 128 * PPAD + (arow + 64 * s) * PPAD + ac4];
            d[0] = to_tf32(rA[s].x); d[1] = to_tf32(rA[s].y);
            d[2] = to_tf32(rA[s].z); d[3] = to_tf32(rA[s].w);
        }
#pragma unroll
        for (int s = 0; s < 4; s++) {
            float* d = &sW[p * 256 * PPAD + (arow + 64 * s) * PPAD + ac4];
            d[0] = to_tf32(rW[s].x); d[1] = to_tf32(rW[s].y);
            d[2] = to_tf32(rW[s].z); d[3] = to_tf32(rW[s].w);
        }
    };

    LOAD(0);
    for (int kc = 0; kc < 64; kc++) {
        const int p = kc & 1;
        STORE(p);
        __syncthreads();
        if (kc + 1 < 64) LOAD(kc + 1);
#pragma unroll
        for (int ks = 0; ks < 2; ks++) {
            const int k0 = ks * 8;
            uint32_t af[4][4], bf[8][2];
#pragma unroll
            for (int mt = 0; mt < 4; mt++) {
                const float* base =
                    &sA[p * 128 * PPAD + (wm * 64 + mt * 16 + g) * PPAD + k0];
                af[mt][0] = __float_as_uint(base[tig]);
                af[mt][1] = __float_as_uint(base[8 * PPAD + tig]);
                af[mt][2] = __float_as_uint(base[tig + 4]);
                af[mt][3] = __float_as_uint(base[8 * PPAD + tig + 4]);
            }
#pragma unroll
            for (int nt = 0; nt < 8; nt++) {
                const float* base =
                    &sW[p * 256 * PPAD + (wn * 64 + nt * 8 + g) * PPAD + k0];
                bf[nt][0] = __float_as_uint(base[tig]);
                bf[nt][1] = __float_as_uint(base[tig + 4]);
            }
#pragma unroll
            for (int mt = 0; mt < 4; mt++)
#pragma unroll
                for (int nt = 0; nt < 8; nt++)
                    mma8(acc[mt][nt], af[mt], bf[nt]);
        }
        __syncthreads();
    }
    // epilogue: write tf32-rounded fp32 so attention mma is exact on them
#pragma unroll
    for (int mt = 0; mt < 4; mt++) {
        const int r0 = m0 + wm * 64 + mt * 16 + g;
#pragma unroll
        for (int nt = 0; nt < 8; nt++) {
            const int c0 = n0 + wn * 64 + nt * 8 + tig * 2;
            float2 v0 = make_float2(to_tf32(acc[mt][nt][0]), to_tf32(acc[mt][nt][1]));
            float2 v1 = make_float2(to_tf32(acc[mt][nt][2]), to_tf32(acc[mt][nt][3]));
            *(float2*)&C[(size_t)r0 * EDIM + c0] = v0;
            *(float2*)&C[(size_t)(r0 + 8) * EDIM + c0] = v1;
        }
    }
}

// ================= attention energies =================
// Block (kt,h,b): q = MMA rows, k = MMA cols. K fragments hoisted in regs.
// Q streamed via cp.async double buffer (NQ=128 rows/iter, 32 iters).
#define APAD 68
#define EXS  0.1803368801111f   /* 0.125 * log2(e) */

__global__ void __launch_bounds__(256, 1)
attn_tc(const float* __restrict__ Qp, const float* __restrict__ Kp,
        float* __restrict__ out) {
    extern __shared__ float sm[];
    float* Ks  = sm;                    // 128 * APAD
    float* Qs  = sm + 128 * APAD;       // 2 * 128 * APAD
    float* red = sm + 3 * 128 * APAD;   // 256
    const int tid = threadIdx.x, lane = tid & 31, wid = tid >> 5;
    const int wm = wid & 1, wn = wid >> 1, g = lane >> 2, tig = lane & 3;
    const int kt = blockIdx.x, h = blockIdx.y, b = blockIdx.z;

    // K tile 128 x 64 (already exact tf32 bits from proj epilogue)
    {
        const float* kp = Kp + ((size_t)(b * LSEQ + kt * 128)) * EDIM + h * HD;
#pragma unroll
        for (int s = 0; s < 8; s++) {
            int f = tid + 256 * s, row = f >> 4, c4 = (f & 15) * 4;
            *(float4*)&Ks[row * APAD + c4] =
                *(const float4*)(kp + (size_t)row * EDIM + c4);
        }
    }
    __syncthreads();
    // Hoist K fragments: B operand, col = k index, row = d
    uint32_t kf[4][8][2];
#pragma unroll
    for (int nt = 0; nt < 4; nt++) {
        const float* base = &Ks[(wn * 32 + nt * 8 + g) * APAD];
#pragma unroll
        for (int ks = 0; ks < 8; ks++) {
            kf[nt][ks][0] = __float_as_uint(base[ks * 8 + tig]);
            kf[nt][ks][1] = __float_as_uint(base[ks * 8 + tig + 4]);
        }
    }

    const uint32_t qsb = smem_u32(Qs);
    auto ISSUE = [&](int i, int p) {
        const int qbase = (i >> 2) * LSEQ + (i & 3) * 128;
        const float* src0 = Qp + (size_t)qbase * EDIM + h * HD;
        const uint32_t dst0 = qsb + (uint32_t)p * 128 * APAD * 4;
#pragma unroll
        for (int s = 0; s < 8; s++) {
            int f = tid + 256 * s, row = f >> 4, c16 = f & 15;
            CP16(dst0 + (uint32_t)(row * APAD + c16 * 4) * 4,
                 src0 + (size_t)row * EDIM + c16 * 4);
        }
        CP_COMMIT();
    };

    float energy = 0.f;
    float colsum[4][2];
    ISSUE(0, 0);
    for (int i = 0; i < 32; i++) {
        const int p = i & 1;
        if (i + 1 < 32) { ISSUE(i + 1, p ^ 1); CP_WAIT(1); }
        else            { CP_WAIT(0); }
        __syncthreads();
        if ((i & 3) == 0) {
#pragma unroll
            for (int nt = 0; nt < 4; nt++) { colsum[nt][0] = 0.f; colsum[nt][1] = 0.f; }
        }
        float acc[4][4][4];
#pragma unroll
        for (int a1 = 0; a1 < 4; a1++)
#pragma unroll
            for (int a2 = 0; a2 < 4; a2++)
#pragma unroll
                for (int a3 = 0; a3 < 4; a3++) acc[a1][a2][a3] = 0.f;
#pragma unroll
        for (int ks = 0; ks < 8; ks++) {
            uint32_t qf[4][4];
#pragma unroll
            for (int mt = 0; mt < 4; mt++) {
                const float* base =
                    &Qs[p * 128 * APAD + (wm * 64 + mt * 16 + g) * APAD + ks * 8];
                qf[mt][0] = __float_as_uint(base[tig]);
                qf[mt][1] = __float_as_uint(base[8 * APAD + tig]);
                qf[mt][2] = __float_as_uint(base[tig + 4]);
                qf[mt][3] = __float_as_uint(base[8 * APAD + tig + 4]);
            }
#pragma unroll
            for (int mt = 0; mt < 4; mt++)
#pragma unroll
                for (int nt = 0; nt < 4; nt++)
                    mma8(acc[mt][nt], qf[mt], kf[nt][ks]);
        }
        // exp + accumulate per k-column (sum over q rows is thread-local + shfl)
#pragma unroll
        for (int mt = 0; mt < 4; mt++)
#pragma unroll
            for (int nt = 0; nt < 4; nt++) {
                colsum[nt][0] += fast_ex2(acc[mt][nt][0] * EXS)
                               + fast_ex2(acc[mt][nt][2] * EXS);
                colsum[nt][1] += fast_ex2(acc[mt][nt][1] * EXS)
                               + fast_ex2(acc[mt][nt][3] * EXS);
            }
        if ((i & 3) == 3) {   // finished one 'a': reduce + log
#pragma unroll
            for (int nt = 0; nt < 4; nt++)
#pragma unroll
                for (int c2 = 0; c2 < 2; c2++) {
                    float v = colsum[nt][c2];
                    v += __shfl_xor_sync(0xffffffffu, v, 4);
                    v += __shfl_xor_sync(0xffffffffu, v, 8);
                    v += __shfl_xor_sync(0xffffffffu, v, 16);
                    if (g == 0)
                        red[wm * 128 + wn * 32 + nt * 8 + tig * 2 + c2] = v;
                }
            __syncthreads();
            if (tid < 128)
                energy += 0.69314718056f * fast_lg2(red[tid] + red[128 + tid]);
        }
        __syncthreads();
    }
    if (tid < 128)
        out[((size_t)(b * NH + h)) * LSEQ + kt * 128 + tid] = energy;
}

// ================= host =================
#define P_SMEM ((2 * 128 * PPAD + 2 * 256 * PPAD) * 4)
#define A_SMEM ((3 * 128 * APAD + 256) * 4)

extern "C" void kernel_launch(void* const* d_in, const int* in_sizes, int n_in,
                              void* d_out, int out_size) {
    (void)in_sizes; (void)n_in; (void)out_size;
    const float* query  = (const float*)d_in[0];
    const float* memory = (const float*)d_in[1];
    const float* W_Q    = (const float*)d_in[2];
    const float* W_K    = (const float*)d_in[3];
    float* out = (float*)d_out;

    float *qp, *kp;
    cudaGetSymbolAddress((void**)&qp, g_Qp);
    cudaGetSymbolAddress((void**)&kp, g_Kp);

    cudaFuncSetAttribute(proj_tc, cudaFuncAttributeMaxDynamicSharedMemorySize, P_SMEM);
    cudaFuncSetAttribute(attn_tc, cudaFuncAttributeMaxDynamicSharedMemorySize, A_SMEM);

    dim3 gP(EDIM / 256, (NB * LSEQ) / 128);   // 4 x 32 = 128 blocks
    proj_tc<<<gP, 256, P_SMEM>>>(query,  W_Q, qp);
    proj_tc<<<gP, 256, P_SMEM>>>(memory, W_K, kp);

    dim3 gA(LSEQ / 128, NH, NB);              // 4 x 16 x 8 = 512 blocks
    attn_tc<<<gA, 256, A_SMEM>>>(qp, kp, out);
}